// round 1
// baseline (speedup 1.0000x reference)
#include <cuda_runtime.h>
#include <math.h>

#define N0 50000
#define E0 1600000
#define K1 40000
#define K2 32000

// ---------------- scratch (device globals; no runtime allocation) ----------------
__device__ float g_x1[N0*128];
__device__ float g_agg[N0*128];
__device__ float g_xp1[K1*128];
__device__ float g_x2[K1*64];
__device__ float g_xp2[K2*64];
__device__ float g_x3[K2*64];
__device__ float g_u1[K1*64];
__device__ float g_x4[K1*128];
__device__ float g_u2[N0*128];
__device__ float g_x5[N0*128];
__device__ int   g_rowptr[N0+1];
__device__ int   g_fill[N0];
__device__ int   g_esrc[E0];
__device__ float g_score[N0];
__device__ unsigned g_key[N0];
__device__ int   g_map1[N0];
__device__ int   g_perm1[K1];
__device__ int   g_map2[K1];
__device__ int   g_perm2[K2];
__device__ int   g_map02[N0];
__device__ int   g_perm02[K2];
__device__ float g_wT[10*128*128];
__device__ float g_norm;
__device__ unsigned g_hist[256];
__device__ unsigned g_prefix;
__device__ int   g_remaining;
__device__ int   g_countG;

// ---------------- small utility kernels ----------------
__global__ void transpose_kernel(const float* __restrict__ w, float* __restrict__ wt, int co, int ci)
{
    int idx = blockIdx.x*blockDim.x + threadIdx.x;
    if (idx < co*ci){ int r = idx/ci, c = idx%ci; wt[c*co + r] = w[idx]; }
}

__global__ void zero_int_kernel(int* p, int n)
{
    int i = blockIdx.x*blockDim.x + threadIdx.x;
    if (i < n) p[i] = 0;
}

__global__ void edge_count_kernel(const int* __restrict__ dst)
{
    int e = blockIdx.x*blockDim.x + threadIdx.x;
    if (e < E0) atomicAdd(&g_fill[dst[e]], 1);
}

__device__ __forceinline__ int block_scan_incl(int val, int& total, int* ws)
{
    int lane = threadIdx.x & 31, wid = threadIdx.x >> 5;
    int x = val;
    #pragma unroll
    for (int off = 1; off < 32; off <<= 1){
        int y = __shfl_up_sync(0xffffffffu, x, off);
        if (lane >= off) x += y;
    }
    if (lane == 31) ws[wid] = x;
    __syncthreads();
    if (wid == 0){
        int s = ws[lane];
        #pragma unroll
        for (int off = 1; off < 32; off <<= 1){
            int y = __shfl_up_sync(0xffffffffu, s, off);
            if (lane >= off) s += y;
        }
        ws[lane] = s;
    }
    __syncthreads();
    int res = x + (wid ? ws[wid-1] : 0);
    total = ws[31];
    __syncthreads();
    return res;
}

// single-block exclusive scan, blockDim must be 1024
__global__ void scan_kernel(const int* __restrict__ in, int* __restrict__ out, int n)
{
    __shared__ int ws[32];
    int run = 0;
    for (int base = 0; base < n; base += 1024){
        int i = base + threadIdx.x;
        int v = (i < n) ? in[i] : 0;
        int tot; int incl = block_scan_incl(v, tot, ws);
        if (i < n) out[i] = run + incl - v;
        run += tot;
    }
    if (threadIdx.x == 0) out[n] = run;
}

__global__ void edge_scatter_kernel(const int* __restrict__ src, const int* __restrict__ dst)
{
    int e = blockIdx.x*blockDim.x + threadIdx.x;
    if (e < E0){
        int d = dst[e];
        int pos = g_rowptr[d] + atomicAdd(&g_fill[d], 1);
        g_esrc[pos] = src[e];
    }
}

// ---------------- aggregation: sum_{j->i} x[j] over CSR rows ----------------
template<int C>
__global__ void agg_kernel(const float* __restrict__ xin, float* __restrict__ agg,
                           const int* __restrict__ perm, const int* __restrict__ mapping)
{
    __shared__ int s_src[C];
    int i = blockIdx.x;
    int old = perm ? perm[i] : i;
    int beg = g_rowptr[old], end = g_rowptr[old+1];
    float acc = 0.f;
    for (int b = beg; b < end; b += C){
        int cnt = min(C, end - b);
        __syncthreads();
        if ((int)threadIdx.x < cnt){
            int s = g_esrc[b + threadIdx.x];
            if (mapping) s = mapping[s];
            s_src[threadIdx.x] = s;
        }
        __syncthreads();
        for (int j = 0; j < cnt; j++){
            int s = s_src[j];
            if (s >= 0) acc += xin[(size_t)s*C + threadIdx.x];
        }
    }
    agg[(size_t)i*C + threadIdx.x] = acc;
}

// ---------------- fused dual GEMM: out = relu(A1*W1t + A2*W2t + b) ----------------
template<int BN, int CIN>
__global__ void __launch_bounds__(256) conv_gemm_kernel(
    const float* __restrict__ A1, const float* __restrict__ A2,
    const float* __restrict__ W1, const float* __restrict__ W2,   // transposed [CIN][BN]
    const float* __restrict__ bias, float* __restrict__ out, int n)
{
    constexpr int BM = 128, BK = 16, TM = 8, TN = BN/16;
    __shared__ float As[BK][BM+4];
    __shared__ float Bs[BK][BN];
    int tid = threadIdx.x;
    int ty = tid >> 4, tx = tid & 15;
    int row0 = blockIdx.x * BM;
    float acc[TM][TN];
    #pragma unroll
    for (int i = 0; i < TM; i++)
        #pragma unroll
        for (int j = 0; j < TN; j++) acc[i][j] = 0.f;

    #pragma unroll
    for (int ph = 0; ph < 2; ph++){
        const float* A = ph ? A2 : A1;
        const float* W = ph ? W2 : W1;
        for (int k0 = 0; k0 < CIN; k0 += BK){
            #pragma unroll
            for (int l = tid; l < BM*BK; l += 256){
                int m = l >> 4, kk = l & 15;
                int r = row0 + m;
                As[kk][m] = (r < n) ? A[(size_t)r*CIN + k0 + kk] : 0.f;
            }
            #pragma unroll
            for (int l = tid; l < BK*BN; l += 256){
                int kk = l / BN, c = l % BN;
                Bs[kk][c] = W[(k0+kk)*BN + c];
            }
            __syncthreads();
            #pragma unroll
            for (int kk = 0; kk < BK; kk++){
                float a[TM], b[TN];
                #pragma unroll
                for (int i = 0; i < TM; i++) a[i] = As[kk][ty*TM + i];
                #pragma unroll
                for (int j = 0; j < TN; j++) b[j] = Bs[kk][tx*TN + j];
                #pragma unroll
                for (int i = 0; i < TM; i++)
                    #pragma unroll
                    for (int j = 0; j < TN; j++) acc[i][j] += a[i]*b[j];
            }
            __syncthreads();
        }
    }
    #pragma unroll
    for (int i = 0; i < TM; i++){
        int r = row0 + ty*TM + i;
        if (r < n){
            #pragma unroll
            for (int j = 0; j < TN; j++){
                float v = acc[i][j] + __ldg(&bias[tx*TN + j]);
                out[(size_t)r*BN + tx*TN + j] = fmaxf(v, 0.f);
            }
        }
    }
}

// ---------------- topk pooling ----------------
template<int C>
__global__ void norm_kernel(const float* __restrict__ w)
{
    int lane = threadIdx.x;
    float p = 0.f;
    #pragma unroll
    for (int i = 0; i < C/32; i++){ float v = w[i*32 + lane]; p += v*v; }
    #pragma unroll
    for (int off = 16; off; off >>= 1) p += __shfl_xor_sync(0xffffffffu, p, off);
    if (lane == 0) g_norm = sqrtf(p);
}

template<int C>
__global__ void score_kernel(const float* __restrict__ x, const float* __restrict__ w, int n)
{
    int gw = blockIdx.x*(blockDim.x>>5) + (threadIdx.x>>5);
    int lane = threadIdx.x & 31;
    if (gw >= n) return;
    float p = 0.f;
    #pragma unroll
    for (int i = 0; i < C/32; i++)
        p += x[(size_t)gw*C + i*32 + lane] * __ldg(&w[i*32 + lane]);
    #pragma unroll
    for (int off = 16; off; off >>= 1) p += __shfl_xor_sync(0xffffffffu, p, off);
    if (lane == 0){
        float s = tanhf(p / g_norm);
        g_score[gw] = s;
        unsigned u = __float_as_uint(s);
        u = (u & 0x80000000u) ? ~u : (u | 0x80000000u);
        g_key[gw] = u;
    }
}

__global__ void sel_init_kernel(int k)
{
    int t = threadIdx.x;
    if (t < 256) g_hist[t] = 0;
    if (t == 0){ g_prefix = 0; g_remaining = k; g_countG = 0; }
}

__global__ void sel_hist_kernel(int n, int pass)
{
    __shared__ unsigned sh[256];
    for (int t = threadIdx.x; t < 256; t += blockDim.x) sh[t] = 0;
    __syncthreads();
    int i = blockIdx.x*blockDim.x + threadIdx.x;
    if (i < n){
        unsigned key = g_key[i];
        bool ok;
        if (pass == 3) ok = true;
        else { int shf = (pass+1)*8; ok = ((key >> shf) == (g_prefix >> shf)); }
        if (ok) atomicAdd(&sh[(key >> (pass*8)) & 255], 1u);
    }
    __syncthreads();
    for (int t = threadIdx.x; t < 256; t += blockDim.x){
        unsigned v = sh[t]; if (v) atomicAdd(&g_hist[t], v);
    }
}

__global__ void sel_scan_kernel(int pass)
{
    if (threadIdx.x == 0){
        unsigned r = (unsigned)g_remaining;
        unsigned c = 0; int b = 255;
        for (; b > 0; b--){
            unsigned h = g_hist[b];
            if (c + h >= r) break;
            c += h;
        }
        g_prefix |= ((unsigned)b) << (pass*8);
        g_remaining = (int)(r - c);
    }
    __syncthreads();
    for (int t = threadIdx.x; t < 256; t += blockDim.x) g_hist[t] = 0;
}

__global__ void sel_count_kernel(int n)
{
    int i = blockIdx.x*blockDim.x + threadIdx.x;
    int pred = 0;
    if (i < n) pred = (g_key[i] > g_prefix) ? 1 : 0;
    int c = __syncthreads_count(pred);
    if (threadIdx.x == 0 && c) atomicAdd(&g_countG, c);
}

// single block (1024 threads): mark selected (top-k with lowest-index tie-break), compact
__global__ void compact_kernel(int* __restrict__ mapping, int* __restrict__ perm, int n, int k)
{
    __shared__ int ws[32];
    unsigned thr = g_prefix;
    int need_eq = k - g_countG;
    int run_eq = 0, run_sel = 0;
    for (int base = 0; base < n; base += 1024){
        int i = base + threadIdx.x;
        int gt = 0, eq = 0;
        if (i < n){
            unsigned kv = g_key[i];
            gt = (kv > thr); eq = (kv == thr);
        }
        int tot_eq; int incl_eq = block_scan_incl(eq, tot_eq, ws);
        int excl_eq = incl_eq - eq;
        int sel = gt | (eq & ((run_eq + excl_eq) < need_eq ? 1 : 0));
        int tot_sel; int incl_sel = block_scan_incl(sel, tot_sel, ws);
        if (i < n){
            if (sel){
                int idx = run_sel + incl_sel - 1;
                mapping[i] = idx;
                perm[idx] = i;
            } else mapping[i] = -1;
        }
        run_eq += tot_eq; run_sel += tot_sel;
    }
}

template<int C>
__global__ void gather_pool_kernel(const float* __restrict__ xin, float* __restrict__ xp,
                                   const int* __restrict__ perm)
{
    int j = blockIdx.x, t = threadIdx.x;
    int o = perm[j];
    xp[(size_t)j*C + t] = xin[(size_t)o*C + t] * g_score[o];
}

__global__ void compose_map_kernel()
{
    int i = blockIdx.x*blockDim.x + threadIdx.x;
    if (i < N0){ int m = g_map1[i]; g_map02[i] = (m >= 0) ? g_map2[m] : -1; }
}
__global__ void compose_perm_kernel()
{
    int j = blockIdx.x*blockDim.x + threadIdx.x;
    if (j < K2) g_perm02[j] = g_perm1[g_perm2[j]];
}

template<int C>
__global__ void unpool_kernel(const float* __restrict__ xb, const float* __restrict__ xs,
                              const int* __restrict__ mapping, float* __restrict__ out)
{
    int i = blockIdx.x, t = threadIdx.x;
    int m = mapping[i];
    float v = xb[(size_t)i*C + t];
    if (m >= 0) v += xs[(size_t)m*C + t];
    out[(size_t)i*C + t] = v;
}

// ---------------- final linear + log_softmax (warp per node) ----------------
__global__ void final_kernel(const float* __restrict__ x, const float* __restrict__ lw,
                             const float* __restrict__ lb, float* __restrict__ out, int n)
{
    int gw = blockIdx.x*(blockDim.x>>5) + (threadIdx.x>>5);
    int lane = threadIdx.x & 31;
    if (gw >= n) return;
    float xv[4];
    #pragma unroll
    for (int i = 0; i < 4; i++) xv[i] = x[(size_t)gw*128 + i*32 + lane];
    float lg[10]; float myv = 0.f;
    #pragma unroll
    for (int c = 0; c < 10; c++){
        float p = 0.f;
        #pragma unroll
        for (int i = 0; i < 4; i++) p += xv[i]*__ldg(&lw[c*128 + i*32 + lane]);
        #pragma unroll
        for (int off = 16; off; off >>= 1) p += __shfl_xor_sync(0xffffffffu, p, off);
        p += __ldg(&lb[c]);
        lg[c] = p;
        if (lane == c) myv = p;
    }
    float m = lg[0];
    #pragma unroll
    for (int c = 1; c < 10; c++) m = fmaxf(m, lg[c]);
    float s = 0.f;
    #pragma unroll
    for (int c = 0; c < 10; c++) s += expf(lg[c] - m);
    float lse = m + logf(s);
    if (lane < 10) out[(size_t)gw*10 + lane] = myv - lse;
}

// ---------------- host driver ----------------
extern "C" void kernel_launch(void* const* d_in, const int* in_sizes, int n_in,
                              void* d_out, int out_size)
{
    (void)in_sizes; (void)n_in; (void)out_size;
    const float* x    = (const float*)d_in[0];
    const int*   ei   = (const int*)d_in[1];
    const int*   src0 = ei;
    const int*   dst0 = ei + E0;
    const float *w1r=(const float*)d_in[2], *w1o=(const float*)d_in[3], *b1=(const float*)d_in[4], *p1w=(const float*)d_in[5];
    const float *w2r=(const float*)d_in[6], *w2o=(const float*)d_in[7], *b2=(const float*)d_in[8], *p2w=(const float*)d_in[9];
    const float *w3r=(const float*)d_in[10],*w3o=(const float*)d_in[11],*b3=(const float*)d_in[12];
    const float *w4r=(const float*)d_in[13],*w4o=(const float*)d_in[14],*b4=(const float*)d_in[15];
    const float *w5r=(const float*)d_in[16],*w5o=(const float*)d_in[17],*b5=(const float*)d_in[18];
    const float *lw =(const float*)d_in[19],*lb =(const float*)d_in[20];
    float* out = (float*)d_out;

    float *x1,*agg,*xp1,*x2,*xp2,*x3,*u1,*x4,*u2,*x5,*wT;
    int *rowptr,*fill,*map1,*perm1,*map2,*perm2,*map02,*perm02;
    cudaGetSymbolAddress((void**)&x1, g_x1);
    cudaGetSymbolAddress((void**)&agg, g_agg);
    cudaGetSymbolAddress((void**)&xp1, g_xp1);
    cudaGetSymbolAddress((void**)&x2, g_x2);
    cudaGetSymbolAddress((void**)&xp2, g_xp2);
    cudaGetSymbolAddress((void**)&x3, g_x3);
    cudaGetSymbolAddress((void**)&u1, g_u1);
    cudaGetSymbolAddress((void**)&x4, g_x4);
    cudaGetSymbolAddress((void**)&u2, g_u2);
    cudaGetSymbolAddress((void**)&x5, g_x5);
    cudaGetSymbolAddress((void**)&wT, g_wT);
    cudaGetSymbolAddress((void**)&rowptr, g_rowptr);
    cudaGetSymbolAddress((void**)&fill, g_fill);
    cudaGetSymbolAddress((void**)&map1, g_map1);
    cudaGetSymbolAddress((void**)&perm1, g_perm1);
    cudaGetSymbolAddress((void**)&map2, g_map2);
    cudaGetSymbolAddress((void**)&perm2, g_perm2);
    cudaGetSymbolAddress((void**)&map02, g_map02);
    cudaGetSymbolAddress((void**)&perm02, g_perm02);

    const int W = 16384;
    // transpose weights into [CIN][COUT]
    transpose_kernel<<<(128*128+255)/256,256>>>(w1r, wT+0*W, 128,128);
    transpose_kernel<<<(128*128+255)/256,256>>>(w1o, wT+1*W, 128,128);
    transpose_kernel<<<(64*128+255)/256,256>>>(w2r, wT+2*W, 64,128);
    transpose_kernel<<<(64*128+255)/256,256>>>(w2o, wT+3*W, 64,128);
    transpose_kernel<<<(64*64+255)/256,256>>>(w3r, wT+4*W, 64,64);
    transpose_kernel<<<(64*64+255)/256,256>>>(w3o, wT+5*W, 64,64);
    transpose_kernel<<<(128*64+255)/256,256>>>(w4r, wT+6*W, 128,64);
    transpose_kernel<<<(128*64+255)/256,256>>>(w4o, wT+7*W, 128,64);
    transpose_kernel<<<(128*128+255)/256,256>>>(w5r, wT+8*W, 128,128);
    transpose_kernel<<<(128*128+255)/256,256>>>(w5o, wT+9*W, 128,128);

    // build CSR of level-0 graph keyed by dst
    zero_int_kernel<<<(N0+255)/256,256>>>(fill, N0);
    edge_count_kernel<<<(E0+255)/256,256>>>(dst0);
    scan_kernel<<<1,1024>>>(fill, rowptr, N0);
    zero_int_kernel<<<(N0+255)/256,256>>>(fill, N0);
    edge_scatter_kernel<<<(E0+255)/256,256>>>(src0, dst0);

    // conv1: 128 -> 128 on level 0
    agg_kernel<128><<<N0,128>>>(x, agg, nullptr, nullptr);
    conv_gemm_kernel<128,128><<<(N0+127)/128,256>>>(agg, x, wT+0*W, wT+1*W, b1, x1, N0);

    // pool1 (C=128, n=N0, k=K1)
    norm_kernel<128><<<1,32>>>(p1w);
    score_kernel<128><<<(N0+7)/8,256>>>(x1, p1w, N0);
    sel_init_kernel<<<1,256>>>(K1);
    for (int pass = 3; pass >= 0; pass--){
        sel_hist_kernel<<<(N0+255)/256,256>>>(N0, pass);
        sel_scan_kernel<<<1,256>>>(pass);
    }
    sel_count_kernel<<<(N0+255)/256,256>>>(N0);
    compact_kernel<<<1,1024>>>(map1, perm1, N0, K1);
    gather_pool_kernel<128><<<K1,128>>>(x1, xp1, perm1);

    // conv2: 128 -> 64 on level 1
    agg_kernel<128><<<K1,128>>>(xp1, agg, perm1, map1);
    conv_gemm_kernel<64,128><<<(K1+127)/128,256>>>(agg, xp1, wT+2*W, wT+3*W, b2, x2, K1);

    // pool2 (C=64, n=K1, k=K2)
    norm_kernel<64><<<1,32>>>(p2w);
    score_kernel<64><<<(K1+7)/8,256>>>(x2, p2w, K1);
    sel_init_kernel<<<1,256>>>(K2);
    for (int pass = 3; pass >= 0; pass--){
        sel_hist_kernel<<<(K1+255)/256,256>>>(K1, pass);
        sel_scan_kernel<<<1,256>>>(pass);
    }
    sel_count_kernel<<<(K1+255)/256,256>>>(K1);
    compact_kernel<<<1,1024>>>(map2, perm2, K1, K2);
    gather_pool_kernel<64><<<K2,64>>>(x2, xp2, perm2);

    // composed mappings level0 -> level2
    compose_map_kernel<<<(N0+255)/256,256>>>();
    compose_perm_kernel<<<(K2+255)/256,256>>>();

    // conv3: 64 -> 64 on level 2
    agg_kernel<64><<<K2,64>>>(xp2, agg, perm02, map02);
    conv_gemm_kernel<64,64><<<(K2+127)/128,256>>>(agg, xp2, wT+4*W, wT+5*W, b3, x3, K2);

    // unpool1 + skip: u1 = scatter(x3 via map2) + x2
    unpool_kernel<64><<<K1,64>>>(x2, x3, map2, u1);

    // conv4: 64 -> 128 on level 1
    agg_kernel<64><<<K1,64>>>(u1, agg, perm1, map1);
    conv_gemm_kernel<128,64><<<(K1+127)/128,256>>>(agg, u1, wT+6*W, wT+7*W, b4, x4, K1);

    // unpool2 + skip: u2 = scatter(x4 via map1) + x1
    unpool_kernel<128><<<N0,128>>>(x1, x4, map1, u2);

    // conv5: 128 -> 128 on level 0
    agg_kernel<128><<<N0,128>>>(u2, agg, nullptr, nullptr);
    conv_gemm_kernel<128,128><<<(N0+127)/128,256>>>(agg, u2, wT+8*W, wT+9*W, b5, x5, N0);

    // final linear + log_softmax
    final_kernel<<<(N0+7)/8,256>>>(x5, lw, lb, out, N0);
}

// round 2
// speedup vs baseline: 1.3326x; 1.3326x over previous
#include <cuda_runtime.h>
#include <math.h>

#define N0 50000
#define E0 1600000
#define K1 40000
#define K2 32000

// ---------------- scratch (device globals; no runtime allocation) ----------------
__device__ float g_x1[N0*128];
__device__ float g_agg[N0*128];
__device__ float g_xp1[K1*128];
__device__ float g_t[K1*64];
__device__ float g_x2[K1*64];
__device__ float g_xp2[K2*64];
__device__ float g_x3[K2*64];
__device__ float g_u1[K1*64];
__device__ float g_x4[K1*128];
__device__ float g_u2[N0*128];
__device__ float g_x5[N0*128];
__device__ int   g_rowptr[N0+1];
__device__ int   g_fill[N0];
__device__ int   g_esrc[E0];
__device__ float g_score[N0];
__device__ unsigned g_key[N0];
__device__ int   g_map1[N0];
__device__ int   g_perm1[K1];
__device__ int   g_map2[K1];
__device__ int   g_perm2[K2];
__device__ int   g_map02[N0];
__device__ int   g_perm02[K2];
__device__ float g_wT[10*128*128];
__device__ float g_norm;
__device__ unsigned g_hist[256];
__device__ unsigned g_prefix;
__device__ int   g_remaining;
__device__ int   g_countG;

// ---------------- CSR build ----------------
__global__ void zero_int_kernel(int* p, int n)
{
    int i = blockIdx.x*blockDim.x + threadIdx.x;
    if (i < n) p[i] = 0;
}

__global__ void edge_count_kernel(const int* __restrict__ dst)
{
    int e = blockIdx.x*blockDim.x + threadIdx.x;
    if (e < E0) atomicAdd(&g_fill[dst[e]], 1);
}

__device__ __forceinline__ int block_scan_incl(int val, int& total, int* ws)
{
    int lane = threadIdx.x & 31, wid = threadIdx.x >> 5;
    int x = val;
    #pragma unroll
    for (int off = 1; off < 32; off <<= 1){
        int y = __shfl_up_sync(0xffffffffu, x, off);
        if (lane >= off) x += y;
    }
    if (lane == 31) ws[wid] = x;
    __syncthreads();
    if (wid == 0){
        int s = ws[lane];
        #pragma unroll
        for (int off = 1; off < 32; off <<= 1){
            int y = __shfl_up_sync(0xffffffffu, s, off);
            if (lane >= off) s += y;
        }
        ws[lane] = s;
    }
    __syncthreads();
    int res = x + (wid ? ws[wid-1] : 0);
    total = ws[31];
    __syncthreads();
    return res;
}

// single-block exclusive scan, blockDim must be 1024
__global__ void scan_kernel(const int* __restrict__ in, int* __restrict__ out, int n)
{
    __shared__ int ws[32];
    int run = 0;
    for (int base = 0; base < n; base += 1024){
        int i = base + threadIdx.x;
        int v = (i < n) ? in[i] : 0;
        int tot; int incl = block_scan_incl(v, tot, ws);
        if (i < n) out[i] = run + incl - v;
        run += tot;
    }
    if (threadIdx.x == 0) out[n] = run;
}

// countdown scatter: consumes g_fill (degree) so no re-zero launch needed
__global__ void edge_scatter_kernel(const int* __restrict__ src, const int* __restrict__ dst)
{
    int e = blockIdx.x*blockDim.x + threadIdx.x;
    if (e < E0){
        int d = dst[e];
        int off = atomicSub(&g_fill[d], 1) - 1;
        g_esrc[g_rowptr[d] + off] = src[e];
    }
}

// ---------------- fused transpose of all 10 weight matrices ----------------
__global__ void transpose_all_kernel(
    const float* w0, const float* w1, const float* w2, const float* w3, const float* w4,
    const float* w5, const float* w6, const float* w7, const float* w8, const float* w9,
    float* __restrict__ wT)
{
    const float* ws[10] = {w0,w1,w2,w3,w4,w5,w6,w7,w8,w9};
    const int CO[10] = {128,128,64,64,64,64,128,128,128,128};
    const int CI[10] = {128,128,128,128,64,64,64,64,128,128};
    int m = blockIdx.y;
    int idx = blockIdx.x*blockDim.x + threadIdx.x;
    int nEl = CO[m]*CI[m];
    if (idx < nEl){
        int r = idx / CI[m], c = idx % CI[m];
        wT[m*16384 + c*CO[m] + r] = ws[m][idx];
    }
}

// ---------------- aggregation: warp per node, vectorized row gather ----------------
template<int C>
__global__ void agg_kernel(const float* __restrict__ xin, float* __restrict__ out,
                           const int* __restrict__ perm, const int* __restrict__ mapping, int n)
{
    int warp = (blockIdx.x*blockDim.x + threadIdx.x) >> 5;
    int lane = threadIdx.x & 31;
    if (warp >= n) return;
    int old = perm ? perm[warp] : warp;
    int beg = g_rowptr[old], end = g_rowptr[old+1];
    if constexpr (C == 128){
        float4 acc = make_float4(0.f,0.f,0.f,0.f);
        for (int b = beg; b < end; b += 32){
            int e = b + lane;
            int s = -1;
            if (e < end){ s = g_esrc[e]; if (mapping) s = mapping[s]; }
            int cnt = min(32, end - b);
            for (int j = 0; j < cnt; j++){
                int sj = __shfl_sync(0xffffffffu, s, j);
                if (sj >= 0){
                    float4 v = ((const float4*)(xin + (size_t)sj*128))[lane];
                    acc.x += v.x; acc.y += v.y; acc.z += v.z; acc.w += v.w;
                }
            }
        }
        ((float4*)(out + (size_t)warp*128))[lane] = acc;
    } else {
        float2 acc = make_float2(0.f,0.f);
        for (int b = beg; b < end; b += 32){
            int e = b + lane;
            int s = -1;
            if (e < end){ s = g_esrc[e]; if (mapping) s = mapping[s]; }
            int cnt = min(32, end - b);
            for (int j = 0; j < cnt; j++){
                int sj = __shfl_sync(0xffffffffu, s, j);
                if (sj >= 0){
                    float2 v = ((const float2*)(xin + (size_t)sj*64))[lane];
                    acc.x += v.x; acc.y += v.y;
                }
            }
        }
        ((float2*)(out + (size_t)warp*64))[lane] = acc;
    }
}

// ---------------- GEMM: out = [relu](D + A1*W1t [+ A2*W2t] [+ b]) ----------------
template<int BN, int CIN, bool DUAL, bool RELU>
__global__ void __launch_bounds__(256) gemm_kernel(
    const float* __restrict__ A1, const float* __restrict__ A2,
    const float* __restrict__ W1, const float* __restrict__ W2,   // transposed [CIN][BN]
    const float* __restrict__ bias, const float* __restrict__ D,
    float* __restrict__ out, int n)
{
    constexpr int BM = 128, BK = 16, TM = 8, TN = BN/16;
    __shared__ float As[BK][BM+4];
    __shared__ float Bs[BK][BN];
    int tid = threadIdx.x;
    int ty = tid >> 4, tx = tid & 15;
    int row0 = blockIdx.x * BM;
    float acc[TM][TN];
    #pragma unroll
    for (int i = 0; i < TM; i++)
        #pragma unroll
        for (int j = 0; j < TN; j++) acc[i][j] = 0.f;

    constexpr int NPH = DUAL ? 2 : 1;
    #pragma unroll
    for (int ph = 0; ph < NPH; ph++){
        const float* A = (DUAL && ph) ? A2 : A1;
        const float* W = (DUAL && ph) ? W2 : W1;
        for (int k0 = 0; k0 < CIN; k0 += BK){
            // A tile: BM x BK floats = 512 float4, 2 per thread
            #pragma unroll
            for (int f = tid; f < (BM*BK)/4; f += 256){
                int m = f >> 2;            // row within tile
                int kq = (f & 3) << 2;     // starting k within BK
                int r = row0 + m;
                float4 v = make_float4(0.f,0.f,0.f,0.f);
                if (r < n) v = *(const float4*)(A + (size_t)r*CIN + k0 + kq);
                As[kq+0][m] = v.x; As[kq+1][m] = v.y; As[kq+2][m] = v.z; As[kq+3][m] = v.w;
            }
            // B tile: BK x BN floats, contiguous float4
            #pragma unroll
            for (int f = tid; f < (BK*BN)/4; f += 256){
                int kk = f / (BN/4);
                int c4 = (f % (BN/4)) << 2;
                *(float4*)&Bs[kk][c4] = *(const float4*)(W + (size_t)(k0+kk)*BN + c4);
            }
            __syncthreads();
            #pragma unroll
            for (int kk = 0; kk < BK; kk++){
                float a[TM], b[TN];
                #pragma unroll
                for (int i = 0; i < TM; i++) a[i] = As[kk][ty*TM + i];
                #pragma unroll
                for (int j = 0; j < TN; j++) b[j] = Bs[kk][tx*TN + j];
                #pragma unroll
                for (int i = 0; i < TM; i++)
                    #pragma unroll
                    for (int j = 0; j < TN; j++) acc[i][j] += a[i]*b[j];
            }
            __syncthreads();
        }
    }
    #pragma unroll
    for (int i = 0; i < TM; i++){
        int r = row0 + ty*TM + i;
        if (r < n){
            #pragma unroll
            for (int j4 = 0; j4 < TN; j4 += 4){
                float4 v;
                float* vp = (float*)&v;
                #pragma unroll
                for (int q = 0; q < 4; q++){
                    int c = tx*TN + j4 + q;
                    float x = acc[i][j4+q];
                    if (bias) x += __ldg(&bias[c]);
                    if (D)    x += D[(size_t)r*BN + c];
                    if (RELU) x = fmaxf(x, 0.f);
                    vp[q] = x;
                }
                *(float4*)(out + (size_t)r*BN + tx*TN + j4) = v;
            }
        }
    }
}

// ---------------- topk pooling ----------------
template<int C>
__global__ void norm_kernel(const float* __restrict__ w)
{
    int lane = threadIdx.x;
    float p = 0.f;
    #pragma unroll
    for (int i = 0; i < C/32; i++){ float v = w[i*32 + lane]; p += v*v; }
    #pragma unroll
    for (int off = 16; off; off >>= 1) p += __shfl_xor_sync(0xffffffffu, p, off);
    if (lane == 0) g_norm = sqrtf(p);
}

template<int C>
__global__ void score_kernel(const float* __restrict__ x, const float* __restrict__ w, int n)
{
    int gw = blockIdx.x*(blockDim.x>>5) + (threadIdx.x>>5);
    int lane = threadIdx.x & 31;
    if (gw >= n) return;
    float p;
    if constexpr (C == 128){
        float4 xv = ((const float4*)(x + (size_t)gw*128))[lane];
        float4 wv = ((const float4*)w)[lane];
        p = xv.x*wv.x + xv.y*wv.y + xv.z*wv.z + xv.w*wv.w;
    } else {
        float2 xv = ((const float2*)(x + (size_t)gw*64))[lane];
        float2 wv = ((const float2*)w)[lane];
        p = xv.x*wv.x + xv.y*wv.y;
    }
    #pragma unroll
    for (int off = 16; off; off >>= 1) p += __shfl_xor_sync(0xffffffffu, p, off);
    if (lane == 0){
        float s = tanhf(p / g_norm);
        g_score[gw] = s;
        unsigned u = __float_as_uint(s);
        u = (u & 0x80000000u) ? ~u : (u | 0x80000000u);
        g_key[gw] = u;
    }
}

__global__ void sel_init_kernel(int k)
{
    int t = threadIdx.x;
    if (t < 256) g_hist[t] = 0;
    if (t == 0){ g_prefix = 0; g_remaining = k; g_countG = 0; }
}

__global__ void sel_hist_kernel(int n, int pass)
{
    __shared__ unsigned sh[256];
    for (int t = threadIdx.x; t < 256; t += blockDim.x) sh[t] = 0;
    __syncthreads();
    int i = blockIdx.x*blockDim.x + threadIdx.x;
    if (i < n){
        unsigned key = g_key[i];
        bool ok;
        if (pass == 3) ok = true;
        else { int shf = (pass+1)*8; ok = ((key >> shf) == (g_prefix >> shf)); }
        if (ok) atomicAdd(&sh[(key >> (pass*8)) & 255], 1u);
    }
    __syncthreads();
    for (int t = threadIdx.x; t < 256; t += blockDim.x){
        unsigned v = sh[t]; if (v) atomicAdd(&g_hist[t], v);
    }
}

__global__ void sel_scan_kernel(int pass)
{
    if (threadIdx.x == 0){
        unsigned r = (unsigned)g_remaining;
        unsigned c = 0; int b = 255;
        for (; b > 0; b--){
            unsigned h = g_hist[b];
            if (c + h >= r) break;
            c += h;
        }
        g_prefix |= ((unsigned)b) << (pass*8);
        g_remaining = (int)(r - c);
    }
    __syncthreads();
    for (int t = threadIdx.x; t < 256; t += blockDim.x) g_hist[t] = 0;
}

__global__ void sel_count_kernel(int n)
{
    int i = blockIdx.x*blockDim.x + threadIdx.x;
    int pred = 0;
    if (i < n) pred = (g_key[i] > g_prefix) ? 1 : 0;
    int c = __syncthreads_count(pred);
    if (threadIdx.x == 0 && c) atomicAdd(&g_countG, c);
}

// single block (1024 threads): mark selected (top-k, lowest-index tie-break), compact
__global__ void compact_kernel(int* __restrict__ mapping, int* __restrict__ perm, int n, int k)
{
    __shared__ int ws[32];
    unsigned thr = g_prefix;
    int need_eq = k - g_countG;
    int run_eq = 0, run_sel = 0;
    for (int base = 0; base < n; base += 1024){
        int i = base + threadIdx.x;
        int gt = 0, eq = 0;
        if (i < n){
            unsigned kv = g_key[i];
            gt = (kv > thr); eq = (kv == thr);
        }
        int tot_eq; int incl_eq = block_scan_incl(eq, tot_eq, ws);
        int excl_eq = incl_eq - eq;
        int sel = gt | (eq & ((run_eq + excl_eq) < need_eq ? 1 : 0));
        int tot_sel; int incl_sel = block_scan_incl(sel, tot_sel, ws);
        if (i < n){
            if (sel){
                int idx = run_sel + incl_sel - 1;
                mapping[i] = idx;
                perm[idx] = i;
            } else mapping[i] = -1;
        }
        run_eq += tot_eq; run_sel += tot_sel;
    }
}

template<int C>
__global__ void gather_pool_kernel(const float* __restrict__ xin, float* __restrict__ xp,
                                   const int* __restrict__ perm, int k)
{
    int idx = blockIdx.x*blockDim.x + threadIdx.x;
    int total = k * (C/4);
    if (idx >= total) return;
    int j = idx / (C/4), t = idx % (C/4);
    int o = perm[j];
    float s = g_score[o];
    float4 v = ((const float4*)(xin + (size_t)o*C))[t];
    v.x *= s; v.y *= s; v.z *= s; v.w *= s;
    ((float4*)(xp + (size_t)j*C))[t] = v;
}

__global__ void compose_map_kernel()
{
    int i = blockIdx.x*blockDim.x + threadIdx.x;
    if (i < N0){ int m = g_map1[i]; g_map02[i] = (m >= 0) ? g_map2[m] : -1; }
}
__global__ void compose_perm_kernel()
{
    int j = blockIdx.x*blockDim.x + threadIdx.x;
    if (j < K2) g_perm02[j] = g_perm1[g_perm2[j]];
}

template<int C>
__global__ void unpool_kernel(const float* __restrict__ xb, const float* __restrict__ xs,
                              const int* __restrict__ mapping, float* __restrict__ out, int n)
{
    int idx = blockIdx.x*blockDim.x + threadIdx.x;
    int total = n * (C/4);
    if (idx >= total) return;
    int i = idx / (C/4), t = idx % (C/4);
    int m = mapping[i];
    float4 v = ((const float4*)(xb + (size_t)i*C))[t];
    if (m >= 0){
        float4 w = ((const float4*)(xs + (size_t)m*C))[t];
        v.x += w.x; v.y += w.y; v.z += w.z; v.w += w.w;
    }
    ((float4*)(out + (size_t)i*C))[t] = v;
}

// ---------------- final linear + log_softmax (warp per node) ----------------
__global__ void final_kernel(const float* __restrict__ x, const float* __restrict__ lw,
                             const float* __restrict__ lb, float* __restrict__ out, int n)
{
    int gw = blockIdx.x*(blockDim.x>>5) + (threadIdx.x>>5);
    int lane = threadIdx.x & 31;
    if (gw >= n) return;
    float4 xv = ((const float4*)(x + (size_t)gw*128))[lane];
    float lg[10]; float myv = 0.f;
    #pragma unroll
    for (int c = 0; c < 10; c++){
        float4 wv = ((const float4*)(lw + c*128))[lane];
        float p = xv.x*wv.x + xv.y*wv.y + xv.z*wv.z + xv.w*wv.w;
        #pragma unroll
        for (int off = 16; off; off >>= 1) p += __shfl_xor_sync(0xffffffffu, p, off);
        p += __ldg(&lb[c]);
        lg[c] = p;
        if (lane == c) myv = p;
    }
    float m = lg[0];
    #pragma unroll
    for (int c = 1; c < 10; c++) m = fmaxf(m, lg[c]);
    float s = 0.f;
    #pragma unroll
    for (int c = 0; c < 10; c++) s += expf(lg[c] - m);
    float lse = m + logf(s);
    if (lane < 10) out[(size_t)gw*10 + lane] = myv - lse;
}

// ---------------- host driver ----------------
extern "C" void kernel_launch(void* const* d_in, const int* in_sizes, int n_in,
                              void* d_out, int out_size)
{
    (void)in_sizes; (void)n_in; (void)out_size;
    const float* x    = (const float*)d_in[0];
    const int*   ei   = (const int*)d_in[1];
    const int*   src0 = ei;
    const int*   dst0 = ei + E0;
    const float *w1r=(const float*)d_in[2], *w1o=(const float*)d_in[3], *b1=(const float*)d_in[4], *p1w=(const float*)d_in[5];
    const float *w2r=(const float*)d_in[6], *w2o=(const float*)d_in[7], *b2=(const float*)d_in[8], *p2w=(const float*)d_in[9];
    const float *w3r=(const float*)d_in[10],*w3o=(const float*)d_in[11],*b3=(const float*)d_in[12];
    const float *w4r=(const float*)d_in[13],*w4o=(const float*)d_in[14],*b4=(const float*)d_in[15];
    const float *w5r=(const float*)d_in[16],*w5o=(const float*)d_in[17],*b5=(const float*)d_in[18];
    const float *lw =(const float*)d_in[19],*lb =(const float*)d_in[20];
    float* out = (float*)d_out;

    float *x1,*agg,*xp1,*tbuf,*x2,*xp2,*x3,*u1,*x4,*u2,*x5,*wT;
    int *rowptr,*fill,*map1,*perm1,*map2,*perm2,*map02,*perm02;
    cudaGetSymbolAddress((void**)&x1, g_x1);
    cudaGetSymbolAddress((void**)&agg, g_agg);
    cudaGetSymbolAddress((void**)&xp1, g_xp1);
    cudaGetSymbolAddress((void**)&tbuf, g_t);
    cudaGetSymbolAddress((void**)&x2, g_x2);
    cudaGetSymbolAddress((void**)&xp2, g_xp2);
    cudaGetSymbolAddress((void**)&x3, g_x3);
    cudaGetSymbolAddress((void**)&u1, g_u1);
    cudaGetSymbolAddress((void**)&x4, g_x4);
    cudaGetSymbolAddress((void**)&u2, g_u2);
    cudaGetSymbolAddress((void**)&x5, g_x5);
    cudaGetSymbolAddress((void**)&wT, g_wT);
    cudaGetSymbolAddress((void**)&rowptr, g_rowptr);
    cudaGetSymbolAddress((void**)&fill, g_fill);
    cudaGetSymbolAddress((void**)&map1, g_map1);
    cudaGetSymbolAddress((void**)&perm1, g_perm1);
    cudaGetSymbolAddress((void**)&map2, g_map2);
    cudaGetSymbolAddress((void**)&perm2, g_perm2);
    cudaGetSymbolAddress((void**)&map02, g_map02);
    cudaGetSymbolAddress((void**)&perm02, g_perm02);

    const int W = 16384;

    // --- CSR build (4 launches), then transposes (1), then conv1 agg = launch #6 for ncu ---
    zero_int_kernel<<<(N0+255)/256,256>>>(fill, N0);                  // 1
    edge_count_kernel<<<(E0+255)/256,256>>>(dst0);                    // 2
    scan_kernel<<<1,1024>>>(fill, rowptr, N0);                        // 3
    edge_scatter_kernel<<<(E0+255)/256,256>>>(src0, dst0);            // 4
    {
        dim3 g(64, 10);
        transpose_all_kernel<<<g,256>>>(w1r,w1o,w2r,w2o,w3r,w3o,w4r,w4o,w5r,w5o, wT); // 5
    }

    // conv1: 128 -> 128 on level 0
    agg_kernel<128><<<(N0+7)/8,256>>>(x, agg, nullptr, nullptr, N0);  // 6 (profiled)
    gemm_kernel<128,128,true,true><<<(N0+127)/128,256>>>(agg, x, wT+0*W, wT+1*W, b1, nullptr, x1, N0);

    // pool1 (C=128, n=N0, k=K1)
    norm_kernel<128><<<1,32>>>(p1w);
    score_kernel<128><<<(N0+7)/8,256>>>(x1, p1w, N0);
    sel_init_kernel<<<1,256>>>(K1);
    for (int pass = 3; pass >= 0; pass--){
        sel_hist_kernel<<<(N0+255)/256,256>>>(N0, pass);
        sel_scan_kernel<<<1,256>>>(pass);
    }
    sel_count_kernel<<<(N0+255)/256,256>>>(N0);
    compact_kernel<<<1,1024>>>(map1, perm1, N0, K1);
    gather_pool_kernel<128><<<(K1*32+255)/256,256>>>(x1, xp1, perm1, K1);

    // conv2: 128 -> 64 on level 1, transform-before-aggregate (halves edge traffic)
    gemm_kernel<64,128,false,false><<<(K1+127)/128,256>>>(xp1, nullptr, wT+2*W, nullptr, nullptr, nullptr, tbuf, K1);
    agg_kernel<64><<<(K1+7)/8,256>>>(tbuf, agg, perm1, map1, K1);
    gemm_kernel<64,128,false,true><<<(K1+127)/128,256>>>(xp1, nullptr, wT+3*W, nullptr, b2, agg, x2, K1);

    // pool2 (C=64, n=K1, k=K2)
    norm_kernel<64><<<1,32>>>(p2w);
    score_kernel<64><<<(K1+7)/8,256>>>(x2, p2w, K1);
    sel_init_kernel<<<1,256>>>(K2);
    for (int pass = 3; pass >= 0; pass--){
        sel_hist_kernel<<<(K1+255)/256,256>>>(K1, pass);
        sel_scan_kernel<<<1,256>>>(pass);
    }
    sel_count_kernel<<<(K1+255)/256,256>>>(K1);
    compact_kernel<<<1,1024>>>(map2, perm2, K1, K2);
    gather_pool_kernel<64><<<(K2*16+255)/256,256>>>(x2, xp2, perm2, K2);

    // composed mappings level0 -> level2
    compose_map_kernel<<<(N0+255)/256,256>>>();
    compose_perm_kernel<<<(K2+255)/256,256>>>();

    // conv3: 64 -> 64 on level 2
    agg_kernel<64><<<(K2+7)/8,256>>>(xp2, agg, perm02, map02, K2);
    gemm_kernel<64,64,true,true><<<(K2+127)/128,256>>>(agg, xp2, wT+4*W, wT+5*W, b3, nullptr, x3, K2);

    // unpool1 + skip: u1 = scatter(x3 via map2) + x2
    unpool_kernel<64><<<(K1*16+255)/256,256>>>(x2, x3, map2, u1, K1);

    // conv4: 64 -> 128 on level 1
    agg_kernel<64><<<(K1+7)/8,256>>>(u1, agg, perm1, map1, K1);
    gemm_kernel<128,64,true,true><<<(K1+127)/128,256>>>(agg, u1, wT+6*W, wT+7*W, b4, nullptr, x4, K1);

    // unpool2 + skip: u2 = scatter(x4 via map1) + x1
    unpool_kernel<128><<<(N0*32+255)/256,256>>>(x1, x4, map1, u2, N0);

    // conv5: 128 -> 128 on level 0
    agg_kernel<128><<<(N0+7)/8,256>>>(u2, agg, nullptr, nullptr, N0);
    gemm_kernel<128,128,true,true><<<(N0+127)/128,256>>>(agg, u2, wT+8*W, wT+9*W, b5, nullptr, x5, N0);

    // final linear + log_softmax
    final_kernel<<<(N0+7)/8,256>>>(x5, lw, lb, out, N0);
}

// round 3
// speedup vs baseline: 1.3786x; 1.0345x over previous
#include <cuda_runtime.h>
#include <math.h>

#define N0 50000
#define E0 1600000
#define K1 40000
#define K2 32000
#define NB_SCAN 49   // ceil(N0/1024)

// ---------------- scratch (device globals; no runtime allocation) ----------------
__device__ float g_x1[N0*128];
__device__ float g_agg[N0*128];
__device__ float g_t[K1*64];
__device__ float g_x2[K1*64];
__device__ float g_x3[K2*64];
__device__ float g_u1[K1*64];
__device__ float g_x4[K1*128];
__device__ float g_u2[N0*128];
__device__ float g_x5[N0*128];
__device__ int   g_rowptr[N0+1];
__device__ int   g_fill[N0];
__device__ int   g_part[64];
__device__ int   g_partx[66];
__device__ int   g_esrc[E0];
__device__ float g_score[N0];
__device__ unsigned g_key[N0];
__device__ int   g_map1[N0];
__device__ int   g_perm1[K1];
__device__ int   g_map2[K1];
__device__ int   g_perm2[K2];
__device__ int   g_map02[N0];
__device__ int   g_perm02[K2];
__device__ float g_wT[10*128*128];
__device__ float g_norm;
__device__ unsigned g_hist[256];
__device__ unsigned g_prefix;
__device__ int   g_remaining;

// ---------------- CSR build ----------------
__global__ void edge_count_kernel(const int* __restrict__ dst)
{
    int e = blockIdx.x*blockDim.x + threadIdx.x;
    if (e < E0) atomicAdd(&g_fill[dst[e]], 1);
}

__device__ __forceinline__ int block_scan_incl(int val, int& total, int* ws)
{
    int lane = threadIdx.x & 31, wid = threadIdx.x >> 5;
    int x = val;
    #pragma unroll
    for (int off = 1; off < 32; off <<= 1){
        int y = __shfl_up_sync(0xffffffffu, x, off);
        if (lane >= off) x += y;
    }
    if (lane == 31) ws[wid] = x;
    __syncthreads();
    if (wid == 0){
        int s = ws[lane];
        #pragma unroll
        for (int off = 1; off < 32; off <<= 1){
            int y = __shfl_up_sync(0xffffffffu, s, off);
            if (lane >= off) s += y;
        }
        ws[lane] = s;
    }
    __syncthreads();
    int res = x + (wid ? ws[wid-1] : 0);
    total = ws[31];
    __syncthreads();
    return res;
}

// generic single-block exclusive scan (blockDim = 1024)
__global__ void scan_kernel(const int* __restrict__ in, int* __restrict__ out, int n)
{
    __shared__ int ws[32];
    int run = 0;
    for (int base = 0; base < n; base += 1024){
        int i = base + threadIdx.x;
        int v = (i < n) ? in[i] : 0;
        int tot; int incl = block_scan_incl(v, tot, ws);
        if (i < n) out[i] = run + incl - v;
        run += tot;
    }
    if (threadIdx.x == 0) out[n] = run;
}

// per-block reduce of degrees
__global__ void deg_reduce_kernel(const int* __restrict__ in, int* __restrict__ part, int n)
{
    __shared__ int ws[32];
    int i = blockIdx.x*1024 + threadIdx.x;
    int v = (i < n) ? in[i] : 0;
    int lane = threadIdx.x & 31, wid = threadIdx.x >> 5;
    #pragma unroll
    for (int off = 16; off; off >>= 1) v += __shfl_down_sync(0xffffffffu, v, off);
    if (lane == 0) ws[wid] = v;
    __syncthreads();
    if (wid == 0){
        v = ws[lane];
        #pragma unroll
        for (int off = 16; off; off >>= 1) v += __shfl_down_sync(0xffffffffu, v, off);
        if (lane == 0) part[blockIdx.x] = v;
    }
}

// per-block scan + offset -> rowptr
__global__ void deg_apply_kernel(const int* __restrict__ in, const int* __restrict__ partx,
                                 int* __restrict__ rowptr, int n)
{
    __shared__ int ws[32];
    int i = blockIdx.x*1024 + threadIdx.x;
    int v = (i < n) ? in[i] : 0;
    int tot; int incl = block_scan_incl(v, tot, ws);
    if (i < n) rowptr[i] = partx[blockIdx.x] + incl - v;
    if (i == n) rowptr[n] = partx[gridDim.x];
}

// countdown scatter: consumes g_fill (degrees) so no re-zero needed
__global__ void edge_scatter_kernel(const int* __restrict__ src, const int* __restrict__ dst)
{
    int e = blockIdx.x*blockDim.x + threadIdx.x;
    if (e < E0){
        int d = dst[e];
        int off = atomicSub(&g_fill[d], 1) - 1;
        g_esrc[g_rowptr[d] + off] = src[e];
    }
}

// ---------------- fused transpose of all 10 weight matrices ----------------
__global__ void transpose_all_kernel(
    const float* w0, const float* w1, const float* w2, const float* w3, const float* w4,
    const float* w5, const float* w6, const float* w7, const float* w8, const float* w9,
    float* __restrict__ wT)
{
    const float* ws[10] = {w0,w1,w2,w3,w4,w5,w6,w7,w8,w9};
    const int CO[10] = {128,128,64,64,64,64,128,128,128,128};
    const int CI[10] = {128,128,128,128,64,64,64,64,128,128};
    int m = blockIdx.y;
    int idx = blockIdx.x*blockDim.x + threadIdx.x;
    int nEl = CO[m]*CI[m];
    if (idx < nEl){
        int r = idx / CI[m], c = idx % CI[m];
        wT[m*16384 + c*CO[m] + r] = ws[m][idx];
    }
}

// ---------------- aggregation: warp per node, vectorized row gather ----------------
template<int C>
__global__ void agg_kernel(const float* __restrict__ xin, float* __restrict__ out,
                           const int* __restrict__ perm, const int* __restrict__ mapping, int n)
{
    int warp = (blockIdx.x*blockDim.x + threadIdx.x) >> 5;
    int lane = threadIdx.x & 31;
    if (warp >= n) return;
    int old = perm ? perm[warp] : warp;
    int beg = g_rowptr[old], end = g_rowptr[old+1];
    if constexpr (C == 128){
        float4 acc = make_float4(0.f,0.f,0.f,0.f);
        for (int b = beg; b < end; b += 32){
            int e = b + lane;
            int s = -1;
            if (e < end){ s = g_esrc[e]; if (mapping) s = mapping[s]; }
            int cnt = min(32, end - b);
            for (int j = 0; j < cnt; j++){
                int sj = __shfl_sync(0xffffffffu, s, j);
                if (sj >= 0){
                    float4 v = ((const float4*)(xin + (size_t)sj*128))[lane];
                    acc.x += v.x; acc.y += v.y; acc.z += v.z; acc.w += v.w;
                }
            }
        }
        ((float4*)(out + (size_t)warp*128))[lane] = acc;
    } else {
        float2 acc = make_float2(0.f,0.f);
        for (int b = beg; b < end; b += 32){
            int e = b + lane;
            int s = -1;
            if (e < end){ s = g_esrc[e]; if (mapping) s = mapping[s]; }
            int cnt = min(32, end - b);
            for (int j = 0; j < cnt; j++){
                int sj = __shfl_sync(0xffffffffu, s, j);
                if (sj >= 0){
                    float2 v = ((const float2*)(xin + (size_t)sj*64))[lane];
                    acc.x += v.x; acc.y += v.y;
                }
            }
        }
        ((float2*)(out + (size_t)warp*64))[lane] = acc;
    }
}

// ---------------- GEMM: out = [relu](D + A1*W1t [+ A2*W2t] [+ b]) ----------------
// optional row gather + score scale on A (TopK pooling fused into the GEMM)
template<int BN, int CIN, bool DUAL, bool RELU, bool GATHER>
__global__ void __launch_bounds__(256) gemm_kernel(
    const float* __restrict__ A1, const float* __restrict__ A2,
    const float* __restrict__ W1, const float* __restrict__ W2,   // transposed [CIN][BN]
    const float* __restrict__ bias, const float* __restrict__ D,
    float* __restrict__ out, int n,
    const int* __restrict__ perm, const float* __restrict__ score)
{
    constexpr int BM = 128, BK = 16, TM = 8, TN = BN/16;
    constexpr int TPB = 256;
    constexpr int AV = (BM*BK/4)/TPB;       // 2
    constexpr int BV = (BK*BN/4)/TPB;       // 2 (BN=128) / 1 (BN=64)
    constexpr int TILES = CIN/BK;
    constexpr int T = (DUAL?2:1)*TILES;
    __shared__ float As[2][BK][BM+4];
    __shared__ float Bs[2][BK][BN];
    int tid = threadIdx.x;
    int ty = tid >> 4, tx = tid & 15;
    int row0 = blockIdx.x * BM;

    // per-thread A-load geometry (fixed across tiles)
    int am[AV], akq[AV], aar[AV]; float asc[AV];
    #pragma unroll
    for (int u = 0; u < AV; u++){
        int f = tid + u*TPB;
        am[u] = f >> 2; akq[u] = (f & 3) << 2;
        int r = row0 + am[u];
        aar[u] = -1; asc[u] = 1.f;
        if (r < n){
            int ar = r;
            if (GATHER){ ar = perm[r]; asc[u] = score[ar]; }
            aar[u] = ar;
        }
    }
    int bkk[BV], bc4[BV];
    #pragma unroll
    for (int u = 0; u < BV; u++){
        int f = tid + u*TPB;
        bkk[u] = f / (BN/4); bc4[u] = (f % (BN/4)) << 2;
    }

    float4 ra[AV], rb[BV];
    auto load_tile = [&](int t){
        int ph = DUAL ? (t / TILES) : 0;
        int k0 = (t % TILES) * BK;
        const float* A = (DUAL && ph) ? A2 : A1;
        const float* W = (DUAL && ph) ? W2 : W1;
        #pragma unroll
        for (int u = 0; u < AV; u++){
            float4 v = make_float4(0.f,0.f,0.f,0.f);
            if (aar[u] >= 0){
                v = *(const float4*)(A + (size_t)aar[u]*CIN + k0 + akq[u]);
                if (GATHER){ v.x*=asc[u]; v.y*=asc[u]; v.z*=asc[u]; v.w*=asc[u]; }
            }
            ra[u] = v;
        }
        #pragma unroll
        for (int u = 0; u < BV; u++)
            rb[u] = *(const float4*)(W + (size_t)(k0 + bkk[u])*BN + bc4[u]);
    };
    auto store_tile = [&](int buf){
        #pragma unroll
        for (int u = 0; u < AV; u++){
            As[buf][akq[u]+0][am[u]] = ra[u].x;
            As[buf][akq[u]+1][am[u]] = ra[u].y;
            As[buf][akq[u]+2][am[u]] = ra[u].z;
            As[buf][akq[u]+3][am[u]] = ra[u].w;
        }
        #pragma unroll
        for (int u = 0; u < BV; u++)
            *(float4*)&Bs[buf][bkk[u]][bc4[u]] = rb[u];
    };

    float acc[TM][TN];
    #pragma unroll
    for (int i = 0; i < TM; i++)
        #pragma unroll
        for (int j = 0; j < TN; j++) acc[i][j] = 0.f;

    load_tile(0); store_tile(0); __syncthreads();
    for (int t = 0; t < T; t++){
        if (t + 1 < T) load_tile(t + 1);
        int buf = t & 1;
        #pragma unroll
        for (int kk = 0; kk < BK; kk++){
            float a[TM], b[TN];
            #pragma unroll
            for (int i = 0; i < TM; i++) a[i] = As[buf][kk][ty*TM + i];
            #pragma unroll
            for (int j = 0; j < TN; j++) b[j] = Bs[buf][kk][tx*TN + j];
            #pragma unroll
            for (int i = 0; i < TM; i++)
                #pragma unroll
                for (int j = 0; j < TN; j++) acc[i][j] += a[i]*b[j];
        }
        if (t + 1 < T){ store_tile((t+1)&1); __syncthreads(); }
    }

    #pragma unroll
    for (int i = 0; i < TM; i++){
        int r = row0 + ty*TM + i;
        if (r < n){
            #pragma unroll
            for (int j4 = 0; j4 < TN; j4 += 4){
                float4 v;
                float* vp = (float*)&v;
                #pragma unroll
                for (int q = 0; q < 4; q++){
                    int c = tx*TN + j4 + q;
                    float x = acc[i][j4+q];
                    if (bias) x += __ldg(&bias[c]);
                    if (D)    x += D[(size_t)r*BN + c];
                    if (RELU) x = fmaxf(x, 0.f);
                    vp[q] = x;
                }
                *(float4*)(out + (size_t)r*BN + tx*TN + j4) = v;
            }
        }
    }
}

// ---------------- topk pooling ----------------
template<int C>
__global__ void norm_kernel(const float* __restrict__ w)
{
    int lane = threadIdx.x;
    float p = 0.f;
    #pragma unroll
    for (int i = 0; i < C/32; i++){ float v = w[i*32 + lane]; p += v*v; }
    #pragma unroll
    for (int off = 16; off; off >>= 1) p += __shfl_xor_sync(0xffffffffu, p, off);
    if (lane == 0) g_norm = sqrtf(p);
}

template<int C>
__global__ void score_kernel(const float* __restrict__ x, const float* __restrict__ w, int n)
{
    int gw = blockIdx.x*(blockDim.x>>5) + (threadIdx.x>>5);
    int lane = threadIdx.x & 31;
    if (gw >= n) return;
    float p;
    if constexpr (C == 128){
        float4 xv = ((const float4*)(x + (size_t)gw*128))[lane];
        float4 wv = ((const float4*)w)[lane];
        p = xv.x*wv.x + xv.y*wv.y + xv.z*wv.z + xv.w*wv.w;
    } else {
        float2 xv = ((const float2*)(x + (size_t)gw*64))[lane];
        float2 wv = ((const float2*)w)[lane];
        p = xv.x*wv.x + xv.y*wv.y;
    }
    #pragma unroll
    for (int off = 16; off; off >>= 1) p += __shfl_xor_sync(0xffffffffu, p, off);
    if (lane == 0){
        float s = tanhf(p / g_norm);
        g_score[gw] = s;
        unsigned u = __float_as_uint(s);
        u = (u & 0x80000000u) ? ~u : (u | 0x80000000u);
        g_key[gw] = u;
    }
}

__global__ void sel_init_kernel(int k)
{
    int t = threadIdx.x;
    if (t < 256) g_hist[t] = 0;
    if (t == 0){ g_prefix = 0; g_remaining = k; }
}

__global__ void sel_hist_kernel(int n, int pass)
{
    __shared__ unsigned sh[256];
    for (int t = threadIdx.x; t < 256; t += blockDim.x) sh[t] = 0;
    __syncthreads();
    int i = blockIdx.x*blockDim.x + threadIdx.x;
    if (i < n){
        unsigned key = g_key[i];
        bool ok;
        if (pass == 3) ok = true;
        else { int shf = (pass+1)*8; ok = ((key >> shf) == (g_prefix >> shf)); }
        if (ok) atomicAdd(&sh[(key >> (pass*8)) & 255], 1u);
    }
    __syncthreads();
    for (int t = threadIdx.x; t < 256; t += blockDim.x){
        unsigned v = sh[t]; if (v) atomicAdd(&g_hist[t], v);
    }
}

__global__ void sel_scan_kernel(int pass)
{
    if (threadIdx.x == 0){
        unsigned r = (unsigned)g_remaining;
        unsigned c = 0; int b = 255;
        for (; b > 0; b--){
            unsigned h = g_hist[b];
            if (c + h >= r) break;
            c += h;
        }
        g_prefix |= ((unsigned)b) << (pass*8);
        g_remaining = (int)(r - c);
    }
    __syncthreads();
    for (int t = threadIdx.x; t < 256; t += blockDim.x) g_hist[t] = 0;
}

// single block (1024 threads): count strictly-greater, then mark/compact top-k
// (ties at threshold broken by lowest index, matching jax.lax.top_k)
__global__ void compact_kernel(int* __restrict__ mapping, int* __restrict__ perm, int n, int k)
{
    __shared__ int ws[32];
    unsigned thr = g_prefix;
    // pass 1: total strictly-greater count
    int local = 0;
    for (int base = 0; base < n; base += 1024){
        int i = base + threadIdx.x;
        if (i < n) local += (g_key[i] > thr) ? 1 : 0;
    }
    int totG; block_scan_incl(local, totG, ws);
    int need_eq = k - totG;
    // pass 2: compact
    int run_eq = 0, run_sel = 0;
    for (int base = 0; base < n; base += 1024){
        int i = base + threadIdx.x;
        int gt = 0, eq = 0;
        if (i < n){
            unsigned kv = g_key[i];
            gt = (kv > thr); eq = (kv == thr);
        }
        int tot_eq; int incl_eq = block_scan_incl(eq, tot_eq, ws);
        int excl_eq = incl_eq - eq;
        int sel = gt | (eq & ((run_eq + excl_eq) < need_eq ? 1 : 0));
        int tot_sel; int incl_sel = block_scan_incl(sel, tot_sel, ws);
        if (i < n){
            if (sel){
                int idx = run_sel + incl_sel - 1;
                mapping[i] = idx;
                perm[idx] = i;
            } else mapping[i] = -1;
        }
        run_eq += tot_eq; run_sel += tot_sel;
    }
}

__global__ void compose_map_kernel()
{
    int i = blockIdx.x*blockDim.x + threadIdx.x;
    if (i < N0){ int m = g_map1[i]; g_map02[i] = (m >= 0) ? g_map2[m] : -1; }
}
__global__ void compose_perm_kernel()
{
    int j = blockIdx.x*blockDim.x + threadIdx.x;
    if (j < K2) g_perm02[j] = g_perm1[g_perm2[j]];
}

template<int C>
__global__ void unpool_kernel(const float* __restrict__ xb, const float* __restrict__ xs,
                              const int* __restrict__ mapping, float* __restrict__ out, int n)
{
    int idx = blockIdx.x*blockDim.x + threadIdx.x;
    int total = n * (C/4);
    if (idx >= total) return;
    int i = idx / (C/4), t = idx % (C/4);
    int m = mapping[i];
    float4 v = ((const float4*)(xb + (size_t)i*C))[t];
    if (m >= 0){
        float4 w = ((const float4*)(xs + (size_t)m*C))[t];
        v.x += w.x; v.y += w.y; v.z += w.z; v.w += w.w;
    }
    ((float4*)(out + (size_t)i*C))[t] = v;
}

// ---------------- final linear + log_softmax (warp per node) ----------------
__global__ void final_kernel(const float* __restrict__ x, const float* __restrict__ lw,
                             const float* __restrict__ lb, float* __restrict__ out, int n)
{
    int gw = blockIdx.x*(blockDim.x>>5) + (threadIdx.x>>5);
    int lane = threadIdx.x & 31;
    if (gw >= n) return;
    float4 xv = ((const float4*)(x + (size_t)gw*128))[lane];
    float lg[10]; float myv = 0.f;
    #pragma unroll
    for (int c = 0; c < 10; c++){
        float4 wv = ((const float4*)(lw + c*128))[lane];
        float p = xv.x*wv.x + xv.y*wv.y + xv.z*wv.z + xv.w*wv.w;
        #pragma unroll
        for (int off = 16; off; off >>= 1) p += __shfl_xor_sync(0xffffffffu, p, off);
        p += __ldg(&lb[c]);
        lg[c] = p;
        if (lane == c) myv = p;
    }
    float m = lg[0];
    #pragma unroll
    for (int c = 1; c < 10; c++) m = fmaxf(m, lg[c]);
    float s = 0.f;
    #pragma unroll
    for (int c = 0; c < 10; c++) s += expf(lg[c] - m);
    float lse = m + logf(s);
    if (lane < 10) out[(size_t)gw*10 + lane] = myv - lse;
}

// ---------------- host driver ----------------
extern "C" void kernel_launch(void* const* d_in, const int* in_sizes, int n_in,
                              void* d_out, int out_size)
{
    (void)in_sizes; (void)n_in; (void)out_size;
    const float* x    = (const float*)d_in[0];
    const int*   ei   = (const int*)d_in[1];
    const int*   src0 = ei;
    const int*   dst0 = ei + E0;
    const float *w1r=(const float*)d_in[2], *w1o=(const float*)d_in[3], *b1=(const float*)d_in[4], *p1w=(const float*)d_in[5];
    const float *w2r=(const float*)d_in[6], *w2o=(const float*)d_in[7], *b2=(const float*)d_in[8], *p2w=(const float*)d_in[9];
    const float *w3r=(const float*)d_in[10],*w3o=(const float*)d_in[11],*b3=(const float*)d_in[12];
    const float *w4r=(const float*)d_in[13],*w4o=(const float*)d_in[14],*b4=(const float*)d_in[15];
    const float *w5r=(const float*)d_in[16],*w5o=(const float*)d_in[17],*b5=(const float*)d_in[18];
    const float *lw =(const float*)d_in[19],*lb =(const float*)d_in[20];
    float* out = (float*)d_out;

    float *x1,*agg,*tbuf,*x2,*x3,*u1,*x4,*u2,*x5,*wT,*score;
    int *rowptr,*fill,*part,*partx,*map1,*perm1,*map2,*perm2,*map02,*perm02;
    cudaGetSymbolAddress((void**)&x1, g_x1);
    cudaGetSymbolAddress((void**)&agg, g_agg);
    cudaGetSymbolAddress((void**)&tbuf, g_t);
    cudaGetSymbolAddress((void**)&x2, g_x2);
    cudaGetSymbolAddress((void**)&x3, g_x3);
    cudaGetSymbolAddress((void**)&u1, g_u1);
    cudaGetSymbolAddress((void**)&x4, g_x4);
    cudaGetSymbolAddress((void**)&u2, g_u2);
    cudaGetSymbolAddress((void**)&x5, g_x5);
    cudaGetSymbolAddress((void**)&wT, g_wT);
    cudaGetSymbolAddress((void**)&score, g_score);
    cudaGetSymbolAddress((void**)&rowptr, g_rowptr);
    cudaGetSymbolAddress((void**)&fill, g_fill);
    cudaGetSymbolAddress((void**)&part, g_part);
    cudaGetSymbolAddress((void**)&partx, g_partx);
    cudaGetSymbolAddress((void**)&map1, g_map1);
    cudaGetSymbolAddress((void**)&perm1, g_perm1);
    cudaGetSymbolAddress((void**)&map2, g_map2);
    cudaGetSymbolAddress((void**)&perm2, g_perm2);
    cudaGetSymbolAddress((void**)&map02, g_map02);
    cudaGetSymbolAddress((void**)&perm02, g_perm02);

    const int W = 16384;

    // second stream + fork/join events (created fresh each call; tiny host-side leak,
    // kernel_launch only runs a handful of times)
    cudaStream_t s2;
    cudaEvent_t ev1, ev2;
    cudaStreamCreateWithFlags(&s2, cudaStreamNonBlocking);
    cudaEventCreateWithFlags(&ev1, cudaEventDisableTiming);
    cudaEventCreateWithFlags(&ev2, cudaEventDisableTiming);

    // fork: CSR build + conv1 aggregation on s2
    cudaEventRecord(ev1, 0);
    cudaStreamWaitEvent(s2, ev1, 0);
    cudaMemsetAsync(fill, 0, N0*sizeof(int), s2);
    edge_count_kernel<<<(E0+255)/256,256,0,s2>>>(dst0);
    deg_reduce_kernel<<<NB_SCAN,1024,0,s2>>>(fill, part, N0);
    scan_kernel<<<1,1024,0,s2>>>(part, partx, NB_SCAN);
    deg_apply_kernel<<<NB_SCAN,1024,0,s2>>>(fill, partx, rowptr, N0);
    edge_scatter_kernel<<<(E0+255)/256,256,0,s2>>>(src0, dst0);
    agg_kernel<128><<<(N0+7)/8,256,0,s2>>>(x, agg, nullptr, nullptr, N0);
    cudaEventRecord(ev2, s2);

    // main: transposes + conv1 root-half GEMM (overlaps CSR+agg)
    {
        dim3 g(64, 10);
        transpose_all_kernel<<<g,256>>>(w1r,w1o,w2r,w2o,w3r,w3o,w4r,w4o,w5r,w5o, wT);
    }
    gemm_kernel<128,128,false,false,false><<<(N0+127)/128,256>>>(
        x, nullptr, wT+1*W, nullptr, nullptr, nullptr, x1, N0, nullptr, nullptr);

    // join, then conv1 rel-half (in-place D add + bias + relu)
    cudaStreamWaitEvent(0, ev2, 0);
    gemm_kernel<128,128,false,true,false><<<(N0+127)/128,256>>>(
        agg, nullptr, wT+0*W, nullptr, b1, x1, x1, N0, nullptr, nullptr);

    // pool1 (C=128, n=N0, k=K1)
    norm_kernel<128><<<1,32>>>(p1w);
    score_kernel<128><<<(N0+7)/8,256>>>(x1, p1w, N0);
    sel_init_kernel<<<1,256>>>(K1);
    for (int pass = 3; pass >= 0; pass--){
        sel_hist_kernel<<<(N0+255)/256,256>>>(N0, pass);
        sel_scan_kernel<<<1,256>>>(pass);
    }
    compact_kernel<<<1,1024>>>(map1, perm1, N0, K1);

    // conv2: 128 -> 64 on level 1 (gather+scale fused into GEMM A-loads)
    gemm_kernel<64,128,false,false,true><<<(K1+127)/128,256>>>(
        x1, nullptr, wT+2*W, nullptr, nullptr, nullptr, tbuf, K1, perm1, score);
    agg_kernel<64><<<(K1+7)/8,256>>>(tbuf, agg, perm1, map1, K1);
    gemm_kernel<64,128,false,true,true><<<(K1+127)/128,256>>>(
        x1, nullptr, wT+3*W, nullptr, b2, agg, x2, K1, perm1, score);

    // pool2 (C=64, n=K1, k=K2)
    norm_kernel<64><<<1,32>>>(p2w);
    score_kernel<64><<<(K1+7)/8,256>>>(x2, p2w, K1);
    sel_init_kernel<<<1,256>>>(K2);
    for (int pass = 3; pass >= 0; pass--){
        sel_hist_kernel<<<(K1+255)/256,256>>>(K1, pass);
        sel_scan_kernel<<<1,256>>>(pass);
    }
    compact_kernel<<<1,1024>>>(map2, perm2, K1, K2);

    // composed mappings level0 -> level2
    compose_map_kernel<<<(N0+255)/256,256>>>();
    compose_perm_kernel<<<(K2+255)/256,256>>>();

    // conv3: 64 -> 64 on level 2 (gather fused, transform-before-aggregate)
    gemm_kernel<64,64,false,false,true><<<(K2+127)/128,256>>>(
        x2, nullptr, wT+4*W, nullptr, nullptr, nullptr, tbuf, K2, perm2, score);
    agg_kernel<64><<<(K2+7)/8,256>>>(tbuf, agg, perm02, map02, K2);
    gemm_kernel<64,64,false,true,true><<<(K2+127)/128,256>>>(
        x2, nullptr, wT+5*W, nullptr, b3, agg, x3, K2, perm2, score);

    // unpool1 + skip: u1 = x2 + scatter(x3 via map2)
    unpool_kernel<64><<<(K1*16+255)/256,256>>>(x2, x3, map2, u1, K1);

    // conv4: 64 -> 128 on level 1
    agg_kernel<64><<<(K1+7)/8,256>>>(u1, agg, perm1, map1, K1);
    gemm_kernel<128,64,true,true,false><<<(K1+127)/128,256>>>(
        agg, u1, wT+6*W, wT+7*W, b4, nullptr, x4, K1, nullptr, nullptr);

    // unpool2 + skip: u2 = x1 + scatter(x4 via map1)
    unpool_kernel<128><<<(N0*32+255)/256,256>>>(x1, x4, map1, u2, N0);

    // conv5: 128 -> 128 on level 0
    agg_kernel<128><<<(N0+7)/8,256>>>(u2, agg, nullptr, nullptr, N0);
    gemm_kernel<128,128,true,true,false><<<(N0+127)/128,256>>>(
        agg, u2, wT+8*W, wT+9*W, b5, nullptr, x5, N0, nullptr, nullptr);

    // final linear + log_softmax
    final_kernel<<<(N0+7)/8,256>>>(x5, lw, lb, out, N0);
}